// round 2
// baseline (speedup 1.0000x reference)
#include <cuda_runtime.h>
#include <cstdint>

// Problem constants
#define NLUT 59049          // 9^5
#define HW   (1 << 20)      // 1024*1024
#define NPIX (4 * HW)       // B*H*W

// Scratch tables (device globals — no allocation allowed)
// A_tab[pos]   = float4(ch0, ch1, ch2, ch3) at LUT position pos (standard d0..d4 order)
// Q_tab[qpos]  = float4 of channel-4 values for the 2x2 (d3,d4) quad, with qpos indexed
//                as (((d0*9+d1)*9+d2)*9 + d4)*9 + d3   (d3 innermost)
__device__ float4 A_tab[NLUT];
__device__ float4 Q_tab[NLUT];

__global__ void build_tables(const float* __restrict__ lut) {
    int pos = blockIdx.x * blockDim.x + threadIdx.x;
    if (pos >= NLUT) return;

    A_tab[pos] = make_float4(lut[pos],
                             lut[NLUT + pos],
                             lut[2 * NLUT + pos],
                             lut[3 * NLUT + pos]);

    // Decode qpos = (((hi)*9 + d4)*9 + d3)
    int d3 = pos % 9;
    int r  = pos / 9;
    int d4 = r % 9;
    int hi = r / 9;                 // (d0*9+d1)*9+d2
    const float* c4 = lut + 4 * NLUT + hi * 81;   // plane of [d3][d4]
    int d3p = d3 < 8 ? d3 + 1 : 8;
    int d4p = d4 < 8 ? d4 + 1 : 8;
    Q_tab[pos] = make_float4(c4[d3  * 9 + d4 ],
                             c4[d3p * 9 + d4 ],
                             c4[d3  * 9 + d4p],
                             c4[d3p * 9 + d4p]);
}

__global__ __launch_bounds__(256)
void pglut_kernel(const float* __restrict__ x, float* __restrict__ out) {
    int t = blockIdx.x * 256 + threadIdx.x;
    int b = t >> 20;
    int p = t & (HW - 1);

    const float* xb = x + ((size_t)b * 5 << 20) + p;

    float f[5];
    int   idx[5];
#pragma unroll
    for (int c = 0; c < 5; c++) {
        float v  = __ldg(xb + ((size_t)c << 20)) * 8.0f;
        float fl = floorf(v);
        fl = fminf(fmaxf(fl, 0.0f), 7.0f);
        idx[c] = (int)fl;
        f[c]   = v - fl;
    }

    float a0 = 1.0f - f[0], a1 = 1.0f - f[1], a2 = 1.0f - f[2];
    float a3 = 1.0f - f[3], a4 = 1.0f - f[4];

    float w01[4] = {a0 * a1, a0 * f[1], f[0] * a1, f[0] * f[1]};
    float w23[4] = {a2 * a3, a2 * f[3], f[2] * a3, f[2] * f[3]};

    // (d3,d4) quad weights for channel 4
    float waa = a3 * a4, wba = f[3] * a4, wab = a3 * f[4], wbb = f[3] * f[4];

    int base  = idx[0] * 6561 + idx[1] * 729 + idx[2] * 81 + idx[3] * 9 + idx[4];
    int qbase = idx[0] * 6561 + idx[1] * 729 + idx[2] * 81 + idx[4] * 9 + idx[3];

    float acc0 = 0.f, acc1 = 0.f, acc2 = 0.f, acc3 = 0.f, acc4 = 0.f;

    // Channels 0-3: 16 corner-pairs (pair contiguous along d4)
#pragma unroll
    for (int j = 0; j < 16; j++) {
        int off = ((j & 8) ? 6561 : 0) + ((j & 4) ? 729 : 0)
                + ((j & 2) ? 81   : 0) + ((j & 1) ? 9   : 0);
        float4 lo = __ldg(&A_tab[base + off]);
        float4 hi = __ldg(&A_tab[base + off + 1]);
        float W  = w01[j >> 2] * w23[j & 3];
        float Wl = W * a4;
        float Wh = W * f[4];
        acc0 = fmaf(Wl, lo.x, fmaf(Wh, hi.x, acc0));
        acc1 = fmaf(Wl, lo.y, fmaf(Wh, hi.y, acc1));
        acc2 = fmaf(Wl, lo.z, fmaf(Wh, hi.z, acc2));
        acc3 = fmaf(Wl, lo.w, fmaf(Wh, hi.w, acc3));
    }

    // Channel 4: 8 quad loads (each covers the 2x2 of (d3,d4) corners)
#pragma unroll
    for (int k = 0; k < 8; k++) {
        int off = ((k & 4) ? 6561 : 0) + ((k & 2) ? 729 : 0) + ((k & 1) ? 81 : 0);
        float4 q = __ldg(&Q_tab[qbase + off]);
        float w012  = w01[k >> 1] * ((k & 1) ? f[2] : a2);
        float inner = fmaf(waa, q.x, fmaf(wba, q.y, fmaf(wab, q.z, wbb * q.w)));
        acc4 = fmaf(w012, inner, acc4);
    }

    float* ob = out + ((size_t)b * 5 << 20) + p;
    ob[0]           = acc0;
    ob[1 * HW]      = acc1;
    ob[2 * HW]      = acc2;
    ob[3 * HW]      = acc3;
    ob[4 * HW]      = acc4;
}

extern "C" void kernel_launch(void* const* d_in, const int* in_sizes, int n_in,
                              void* d_out, int out_size) {
    // metadata order: x (4*5*1024*1024), LUT (5*9^5). Guard against swap.
    const float* x   = (const float*)d_in[0];
    const float* lut = (const float*)d_in[1];
    if (n_in >= 2 && in_sizes[0] == 5 * NLUT) {  // inputs swapped
        x   = (const float*)d_in[1];
        lut = (const float*)d_in[0];
    }
    float* out = (float*)d_out;

    build_tables<<<(NLUT + 255) / 256, 256>>>(lut);
    pglut_kernel<<<NPIX / 256, 256>>>(x, out);
}

// round 3
// speedup vs baseline: 1.0175x; 1.0175x over previous
#include <cuda_runtime.h>
#include <cuda_fp16.h>
#include <cstdint>

// Problem constants
#define NLUT 59049          // 9^5
#define HW   (1 << 20)      // 1024*1024
#define NPIX (4 * HW)       // B*H*W

// Scratch tables (device globals — no allocation allowed).
// P_tab[pos]  : 8 halves = { ch0..ch3 @ (d0..d3,d4), ch0..ch3 @ (d0..d3,d4+1) }
//               layout: x={ch0_lo,ch1_lo} y={ch2_lo,ch3_lo} z={ch0_hi,ch1_hi} w={ch2_hi,ch3_hi}
// Q2_tab[pos] : 8 halves = channel-4 2x2 (d3,d4)-quad at d2 and at d2+1
//               layout: x={vaa,vba}@d2  y={vab,vbb}@d2  z={vaa,vba}@d2+1  w={vab,vbb}@d2+1
//               (vXY: X = d3 corner, Y = d4 corner; a=+0, b=+1)
__device__ uint4 P_tab[NLUT];
__device__ uint4 Q2_tab[NLUT];

static __device__ __forceinline__ uint32_t pack2(float a, float b) {
    __half2 h = __floats2half2_rn(a, b);
    return *reinterpret_cast<uint32_t*>(&h);
}

__global__ void build_tables(const float* __restrict__ lut) {
    int pos = blockIdx.x * blockDim.x + threadIdx.x;
    if (pos >= NLUT) return;

    int d4 = pos % 9;
    int r1 = pos / 9;
    int d3 = r1 % 9;
    int r2 = r1 / 9;
    int d2 = r2 % 9;

    // ---- P entry: channels 0-3 at d4 and d4+1 (clamped) ----
    int posn = (d4 < 8) ? pos + 1 : pos;
    uint4 p;
    p.x = pack2(lut[pos],            lut[NLUT + pos]);
    p.y = pack2(lut[2 * NLUT + pos], lut[3 * NLUT + pos]);
    p.z = pack2(lut[posn],           lut[NLUT + posn]);
    p.w = pack2(lut[2 * NLUT + posn], lut[3 * NLUT + posn]);
    P_tab[pos] = p;

    // ---- Q2 entry: channel-4 (d3,d4) 2x2 quad at d2 and d2+1 (clamped) ----
    const float* c4 = lut + 4 * NLUT;
    int d3p = d3 < 8 ? d3 + 1 : 8;
    int d4p = d4 < 8 ? d4 + 1 : 8;
    int hi  = r2;                       // (d0*9+d1)*9 + d2
    int hip = (d2 < 8) ? hi + 1 : hi;   // step d2
    int b0  = hi  * 81;                 // plane base (d3*9 + d4 indexing)
    int b1  = hip * 81;
    uint4 q;
    q.x = pack2(c4[b0 + d3  * 9 + d4 ], c4[b0 + d3p * 9 + d4 ]);
    q.y = pack2(c4[b0 + d3  * 9 + d4p], c4[b0 + d3p * 9 + d4p]);
    q.z = pack2(c4[b1 + d3  * 9 + d4 ], c4[b1 + d3p * 9 + d4 ]);
    q.w = pack2(c4[b1 + d3  * 9 + d4p], c4[b1 + d3p * 9 + d4p]);
    Q2_tab[pos] = q;
}

static __device__ __forceinline__ float2 h2f(uint32_t v) {
    return __half22float2(*reinterpret_cast<__half2*>(&v));
}

__global__ __launch_bounds__(256)
void pglut_kernel(const float* __restrict__ x, float* __restrict__ out) {
    int t = blockIdx.x * 256 + threadIdx.x;
    int b = t >> 20;
    int p = t & (HW - 1);

    const float* xb = x + ((size_t)b * 5 << 20) + p;

    float f[5];
    int   idx[5];
#pragma unroll
    for (int c = 0; c < 5; c++) {
        float v  = __ldg(xb + ((size_t)c << 20)) * 8.0f;
        float fl = floorf(v);
        fl = fminf(fmaxf(fl, 0.0f), 7.0f);
        idx[c] = (int)fl;
        f[c]   = v - fl;
    }

    float a0 = 1.0f - f[0], a1 = 1.0f - f[1], a2 = 1.0f - f[2];
    float a3 = 1.0f - f[3], a4 = 1.0f - f[4];

    float w01[4] = {a0 * a1, a0 * f[1], f[0] * a1, f[0] * f[1]};
    float w23[4] = {a2 * a3, a2 * f[3], f[2] * a3, f[2] * f[3]};

    // (d3,d4) quad weights for channel 4
    float waa = a3 * a4, wba = f[3] * a4, wab = a3 * f[4], wbb = f[3] * f[4];

    int base = idx[0] * 6561 + idx[1] * 729 + idx[2] * 81 + idx[3] * 9 + idx[4];

    float acc0 = 0.f, acc1 = 0.f, acc2 = 0.f, acc3 = 0.f, acc4 = 0.f;

    // Channels 0-3: 16 pair-entries (each 128-bit load covers both d4 corners)
#pragma unroll
    for (int j = 0; j < 16; j++) {
        int off = ((j & 8) ? 6561 : 0) + ((j & 4) ? 729 : 0)
                + ((j & 2) ? 81   : 0) + ((j & 1) ? 9   : 0);
        uint4 r = __ldg(&P_tab[base + off]);
        float2 c01l = h2f(r.x);
        float2 c23l = h2f(r.y);
        float2 c01h = h2f(r.z);
        float2 c23h = h2f(r.w);
        float W  = w01[j >> 2] * w23[j & 3];
        float Wl = W * a4;
        float Wh = W * f[4];
        acc0 = fmaf(Wl, c01l.x, fmaf(Wh, c01h.x, acc0));
        acc1 = fmaf(Wl, c01l.y, fmaf(Wh, c01h.y, acc1));
        acc2 = fmaf(Wl, c23l.x, fmaf(Wh, c23h.x, acc2));
        acc3 = fmaf(Wl, c23l.y, fmaf(Wh, c23h.y, acc3));
    }

    // Channel 4: 4 loads, each covering 8 corners (2x2 (d3,d4) quad x both d2 corners)
#pragma unroll
    for (int k = 0; k < 4; k++) {
        int off = ((k & 2) ? 6561 : 0) + ((k & 1) ? 729 : 0);
        uint4 r = __ldg(&Q2_tab[base + off]);
        float2 qa0 = h2f(r.x);   // (vaa, vba) @ d2
        float2 qb0 = h2f(r.y);   // (vab, vbb) @ d2
        float2 qa1 = h2f(r.z);   // @ d2+1
        float2 qb1 = h2f(r.w);
        float inner0 = fmaf(waa, qa0.x, fmaf(wba, qa0.y, fmaf(wab, qb0.x, wbb * qb0.y)));
        float inner1 = fmaf(waa, qa1.x, fmaf(wba, qa1.y, fmaf(wab, qb1.x, wbb * qb1.y)));
        acc4 = fmaf(w01[k], fmaf(a2, inner0, f[2] * inner1), acc4);
    }

    float* ob = out + ((size_t)b * 5 << 20) + p;
    ob[0]      = acc0;
    ob[1 * HW] = acc1;
    ob[2 * HW] = acc2;
    ob[3 * HW] = acc3;
    ob[4 * HW] = acc4;
}

extern "C" void kernel_launch(void* const* d_in, const int* in_sizes, int n_in,
                              void* d_out, int out_size) {
    // metadata order: x (4*5*1024*1024), LUT (5*9^5). Guard against swap.
    const float* x   = (const float*)d_in[0];
    const float* lut = (const float*)d_in[1];
    if (n_in >= 2 && in_sizes[0] == 5 * NLUT) {  // inputs swapped
        x   = (const float*)d_in[1];
        lut = (const float*)d_in[0];
    }
    float* out = (float*)d_out;

    build_tables<<<(NLUT + 255) / 256, 256>>>(lut);
    pglut_kernel<<<NPIX / 256, 256>>>(x, out);
}

// round 5
// speedup vs baseline: 1.8462x; 1.8145x over previous
#include <cuda_runtime.h>
#include <cuda_fp16.h>
#include <cstdint>

// Problem constants
#define NLUT 59049          // 9^5
#define HW   (1 << 20)      // 1024*1024
#define NPIX (4 * HW)       // B*H*W

// Scratch tables (device globals — no allocation allowed).
//
// P_tab: digit order (d0, d1, d4, d2, d3) — d2,d3 innermost so the 4 (d2,d3)
//        corner entries of a pixel sit within a 176B window (~2.4 cache lines).
//   entry: 8 halves = { ch0..ch3 @ d4, ch0..ch3 @ d4+1 }  (d4 clamped)
//   layout: x={ch0_lo,ch1_lo} y={ch2_lo,ch3_lo} z={ch0_hi,ch1_hi} w={ch2_hi,ch3_hi}
//
// Q2_tab: digit order (d2, d3, d4, d0, d1) — d0,d1 innermost (they are the only
//        external corner dims for channel 4; d2/d3/d4 corners are packed in-entry).
//   entry: 8 halves = ch4 2x2 (d3,d4)-quad at d2 and at d2+1
//   layout: x={vaa,vba}@d2  y={vab,vbb}@d2  z={vaa,vba}@d2+1  w={vab,vbb}@d2+1
//   (vXY: X = d3 corner, Y = d4 corner; a=+0, b=+1)
__device__ uint4 P_tab[NLUT];
__device__ uint4 Q2_tab[NLUT];

static __device__ __forceinline__ uint32_t pack2(float a, float b) {
    __half2 h = __floats2half2_rn(a, b);
    return *reinterpret_cast<uint32_t*>(&h);
}

__global__ void build_tables(const float* __restrict__ lut) {
    int pos = blockIdx.x * blockDim.x + threadIdx.x;
    if (pos >= NLUT) return;

    // decode standard order (d0,d1,d2,d3,d4), d4 innermost
    int d4 = pos % 9;
    int r1 = pos / 9;
    int d3 = r1 % 9;
    int r2 = r1 / 9;
    int d2 = r2 % 9;
    int r3 = r2 / 9;
    int d1 = r3 % 9;
    int d0 = r3 / 9;

    // ---- P entry: channels 0-3 at d4 and d4+1 (clamped) ----
    int posn = (d4 < 8) ? pos + 1 : pos;
    uint4 p;
    p.x = pack2(lut[pos],             lut[NLUT + pos]);
    p.y = pack2(lut[2 * NLUT + pos],  lut[3 * NLUT + pos]);
    p.z = pack2(lut[posn],            lut[NLUT + posn]);
    p.w = pack2(lut[2 * NLUT + posn], lut[3 * NLUT + posn]);
    int ppos = (((d0 * 9 + d1) * 9 + d4) * 9 + d2) * 9 + d3;
    P_tab[ppos] = p;

    // ---- Q2 entry: channel-4 (d3,d4) 2x2 quad at d2 and d2+1 (clamped) ----
    const float* c4 = lut + 4 * NLUT;
    int d3p = d3 < 8 ? d3 + 1 : 8;
    int d4p = d4 < 8 ? d4 + 1 : 8;
    int hi  = r2;                       // (d0*9+d1)*9 + d2
    int hip = (d2 < 8) ? hi + 1 : hi;   // step d2
    int b0  = hi  * 81;                 // plane base (d3*9 + d4 indexing)
    int b1  = hip * 81;
    uint4 q;
    q.x = pack2(c4[b0 + d3  * 9 + d4 ], c4[b0 + d3p * 9 + d4 ]);
    q.y = pack2(c4[b0 + d3  * 9 + d4p], c4[b0 + d3p * 9 + d4p]);
    q.z = pack2(c4[b1 + d3  * 9 + d4 ], c4[b1 + d3p * 9 + d4 ]);
    q.w = pack2(c4[b1 + d3  * 9 + d4p], c4[b1 + d3p * 9 + d4p]);
    int qpos = (((d2 * 9 + d3) * 9 + d4) * 9 + d0) * 9 + d1;
    Q2_tab[qpos] = q;
}

static __device__ __forceinline__ float2 h2f(uint32_t v) {
    return __half22float2(*reinterpret_cast<__half2*>(&v));
}

__global__ __launch_bounds__(256, 7)
void pglut_kernel(const float* __restrict__ x, float* __restrict__ out) {
    int t = blockIdx.x * 256 + threadIdx.x;
    int b = t >> 20;
    int p = t & (HW - 1);

    const float* xb = x + ((size_t)b * 5 << 20) + p;

    float f[5];
    int   idx[5];
#pragma unroll
    for (int c = 0; c < 5; c++) {
        float v  = __ldg(xb + ((size_t)c << 20)) * 8.0f;
        float fl = floorf(v);
        fl = fminf(fmaxf(fl, 0.0f), 7.0f);
        idx[c] = (int)fl;
        f[c]   = v - fl;
    }

    float a0 = 1.0f - f[0], a1 = 1.0f - f[1], a2 = 1.0f - f[2];
    float a3 = 1.0f - f[3], a4 = 1.0f - f[4];

    float w01[4] = {a0 * a1, a0 * f[1], f[0] * a1, f[0] * f[1]};
    float w23[4] = {a2 * a3, a2 * f[3], f[2] * a3, f[2] * f[3]};

    // (d3,d4) quad weights for channel 4
    float waa = a3 * a4, wba = f[3] * a4, wab = a3 * f[4], wbb = f[3] * f[4];

    // P index: (d0,d1,d4,d2,d3);  Q2 index: (d2,d3,d4,d0,d1)
    int pbase = ((((idx[0] * 9 + idx[1]) * 9 + idx[4]) * 9 + idx[2]) * 9) + idx[3];
    int qbase = ((((idx[2] * 9 + idx[3]) * 9 + idx[4]) * 9 + idx[0]) * 9) + idx[1];

    float acc0 = 0.f, acc1 = 0.f, acc2 = 0.f, acc3 = 0.f, acc4 = 0.f;

    // Channels 0-3: 16 pair-entries. Corner bits: j3=d0, j2=d1, j1=d2, j0=d3.
    // (d2,d3) innermost -> each (d0,d1) group's 4 loads land in a 176B window.
#pragma unroll
    for (int j = 0; j < 16; j++) {
        int off = ((j & 8) ? 6561 : 0) + ((j & 4) ? 729 : 0)
                + ((j & 2) ? 9    : 0) + ((j & 1) ? 1   : 0);
        uint4 r = __ldg(&P_tab[pbase + off]);
        float2 c01l = h2f(r.x);
        float2 c23l = h2f(r.y);
        float2 c01h = h2f(r.z);
        float2 c23h = h2f(r.w);
        float W  = w01[j >> 2] * w23[j & 3];
        float Wl = W * a4;
        float Wh = W * f[4];
        acc0 = fmaf(Wl, c01l.x, fmaf(Wh, c01h.x, acc0));
        acc1 = fmaf(Wl, c01l.y, fmaf(Wh, c01h.y, acc1));
        acc2 = fmaf(Wl, c23l.x, fmaf(Wh, c23h.x, acc2));
        acc3 = fmaf(Wl, c23l.y, fmaf(Wh, c23h.y, acc3));
    }

    // Channel 4: 4 loads (k1=d0 corner, k0=d1 corner), each covering 8 corners.
    // (d0,d1) innermost -> all 4 loads in a 176B window.
#pragma unroll
    for (int k = 0; k < 4; k++) {
        int off = ((k & 2) ? 9 : 0) + ((k & 1) ? 1 : 0);
        uint4 r = __ldg(&Q2_tab[qbase + off]);
        float2 qa0 = h2f(r.x);   // (vaa, vba) @ d2
        float2 qb0 = h2f(r.y);   // (vab, vbb) @ d2
        float2 qa1 = h2f(r.z);   // @ d2+1
        float2 qb1 = h2f(r.w);
        float inner0 = fmaf(waa, qa0.x, fmaf(wba, qa0.y, fmaf(wab, qb0.x, wbb * qb0.y)));
        float inner1 = fmaf(waa, qa1.x, fmaf(wba, qa1.y, fmaf(wab, qb1.x, wbb * qb1.y)));
        acc4 = fmaf(w01[k], fmaf(a2, inner0, f[2] * inner1), acc4);
    }

    float* ob = out + ((size_t)b * 5 << 20) + p;
    ob[0]      = acc0;
    ob[1 * HW] = acc1;
    ob[2 * HW] = acc2;
    ob[3 * HW] = acc3;
    ob[4 * HW] = acc4;
}

extern "C" void kernel_launch(void* const* d_in, const int* in_sizes, int n_in,
                              void* d_out, int out_size) {
    // metadata order: x (4*5*1024*1024), LUT (5*9^5). Guard against swap.
    const float* x   = (const float*)d_in[0];
    const float* lut = (const float*)d_in[1];
    if (n_in >= 2 && in_sizes[0] == 5 * NLUT) {  // inputs swapped
        x   = (const float*)d_in[1];
        lut = (const float*)d_in[0];
    }
    float* out = (float*)d_out;

    build_tables<<<(NLUT + 255) / 256, 256>>>(lut);
    pglut_kernel<<<NPIX / 256, 256>>>(x, out);
}